// round 15
// baseline (speedup 1.0000x reference)
#include <cuda_runtime.h>
#include <cuda_bf16.h>
#include <cstdint>
#include <cstddef>

#define N_EDGES 640000
#define N_NODES 40000
#define N_NODES_PAD 40064   // 313 * 128
#define DIM 128
#define NRAD 16

// Scratch (allocation-free rule: __device__ globals), padded to tile multiple
__device__ float g_nodes0[(size_t)N_NODES_PAD * DIM];
__device__ float g_nodes1[(size_t)N_NODES_PAD * DIM];
__device__ int   g_idx_is64;

// ---------------------------------------------------------------------------
// Detect whether idx_i buffer is int64 or int32 (odd 32-bit words all zero
// iff int64 with node ids < 2^32).
// ---------------------------------------------------------------------------
__global__ void detect_idx_kernel(const int* __restrict__ idx32) {
    if (blockIdx.x == 0 && threadIdx.x == 0) {
        int f = 1;
        #pragma unroll
        for (int i = 1; i < 64; i += 2)
            if (idx32[i] != 0) f = 0;
        g_idx_is64 = f;
    }
}

// ---------------------------------------------------------------------------
// Edge phase: h[e,d] = (rbf[e,:] . W_rbf[d,:]) * x[e,d], scatter-add.
// Warp per edge; lane owns dims [4*lane, 4*lane+4). Vector RED.128 atomics.
// ---------------------------------------------------------------------------
__device__ __forceinline__ void red_add_v4(float* p, float4 v) {
    asm volatile("red.global.add.v4.f32 [%0], {%1, %2, %3, %4};"
                 :: "l"(p), "f"(v.x), "f"(v.y), "f"(v.z), "f"(v.w)
                 : "memory");
}

__global__ void edge_kernel(const float* __restrict__ x,
                            const float* __restrict__ rbf,
                            const void*  __restrict__ idx,
                            const float* __restrict__ Wrbf)
{
    const int lane = threadIdx.x & 31;
    const int warp = blockIdx.x * (blockDim.x >> 5) + (threadIdx.x >> 5);
    const int nwarps = gridDim.x * (blockDim.x >> 5);

    // Wrbf rows for this lane's 4 dims: w4[j][m] = Wrbf[(4*lane+j)][4m..4m+3]
    float4 w4[4][4];
    #pragma unroll
    for (int j = 0; j < 4; j++)
        #pragma unroll
        for (int m = 0; m < 4; m++)
            w4[j][m] = ((const float4*)Wrbf)[(size_t)(4 * lane + j) * 4 + m];

    const int is64 = g_idx_is64;
    const long long* idx64 = (const long long*)idx;
    const int*       idx32 = (const int*)idx;

    for (int e = warp; e < N_EDGES; e += nwarps) {
        // rbf[e, 0..15] — warp-uniform loads (single sector each)
        const float4* rb = (const float4*)(rbf + (size_t)e * NRAD);
        const float4 r0 = rb[0], r1 = rb[1], r2 = rb[2], r3 = rb[3];

        float proj[4];
        #pragma unroll
        for (int j = 0; j < 4; j++) {
            float s;
            s =         w4[j][0].x * r0.x;
            s = fmaf(w4[j][0].y, r0.y, s);
            s = fmaf(w4[j][0].z, r0.z, s);
            s = fmaf(w4[j][0].w, r0.w, s);
            s = fmaf(w4[j][1].x, r1.x, s);
            s = fmaf(w4[j][1].y, r1.y, s);
            s = fmaf(w4[j][1].z, r1.z, s);
            s = fmaf(w4[j][1].w, r1.w, s);
            s = fmaf(w4[j][2].x, r2.x, s);
            s = fmaf(w4[j][2].y, r2.y, s);
            s = fmaf(w4[j][2].z, r2.z, s);
            s = fmaf(w4[j][2].w, r2.w, s);
            s = fmaf(w4[j][3].x, r3.x, s);
            s = fmaf(w4[j][3].y, r3.y, s);
            s = fmaf(w4[j][3].z, r3.z, s);
            s = fmaf(w4[j][3].w, r3.w, s);
            proj[j] = s;
        }

        const int node = is64 ? (int)idx64[e] : idx32[e];
        const float4 xv = ((const float4*)x)[(size_t)e * 32 + lane];

        float4 v;
        v.x = proj[0] * xv.x;
        v.y = proj[1] * xv.y;
        v.z = proj[2] * xv.z;
        v.w = proj[3] * xv.w;

        red_add_v4(&g_nodes0[(size_t)node * DIM + lane * 4], v);
    }
}

// ---------------------------------------------------------------------------
// Dense layer: B[i,j] = silu(sum_k A[i,k] * W[j,k] + bias[j])
// Block tile 128x128, 256 threads, 8x8 register tile, float4 k-stepping.
// smem: Ws[128][136] (W transposed, Ws[k][j] = W[j][k]) + As[128][132].
// ---------------------------------------------------------------------------
#define WS_S 136
#define AS_S 132
#define L_SMEM_BYTES ((128 * WS_S + 128 * AS_S) * 4)

__global__ void __launch_bounds__(256, 1)
layer_kernel(const float* __restrict__ A,
             float* __restrict__ B,
             const float* __restrict__ W,
             const float* __restrict__ bias)
{
    extern __shared__ float smem[];
    float* Ws = smem;                 // [128][136]
    float* As = smem + 128 * WS_S;    // [128][132]

    const int t = threadIdx.x;

    // Stage W transposed
    for (int i = t; i < 128 * 128; i += 256)
        Ws[(i & 127) * WS_S + (i >> 7)] = W[i];

    // Stage A tile (float4 coalesced)
    const size_t i0 = (size_t)blockIdx.x * 128;
    for (int i = t; i < 128 * 32; i += 256) {
        const int r = i >> 5, c = i & 31;
        *(float4*)&As[r * AS_S + c * 4] = ((const float4*)A)[(i0 + r) * 32 + c];
    }
    __syncthreads();

    const int c0 = (t & 15) * 8;   // 8 output cols
    const int r0 = (t >> 4) * 8;   // 8 output rows

    float acc[8][8];
    #pragma unroll
    for (int i = 0; i < 8; i++)
        #pragma unroll
        for (int j = 0; j < 8; j++) acc[i][j] = 0.f;

    #pragma unroll 2
    for (int k4 = 0; k4 < 32; k4++) {
        float4 a4[8];
        #pragma unroll
        for (int i = 0; i < 8; i++)
            a4[i] = *(const float4*)&As[(r0 + i) * AS_S + k4 * 4];

        #pragma unroll
        for (int kk = 0; kk < 4; kk++) {
            const float* wrow = &Ws[(k4 * 4 + kk) * WS_S + c0];
            const float4 wa = *(const float4*)wrow;
            const float4 wb = *(const float4*)(wrow + 4);
            #pragma unroll
            for (int i = 0; i < 8; i++) {
                const float a = ((const float*)&a4[i])[kk];
                acc[i][0] = fmaf(a, wa.x, acc[i][0]);
                acc[i][1] = fmaf(a, wa.y, acc[i][1]);
                acc[i][2] = fmaf(a, wa.z, acc[i][2]);
                acc[i][3] = fmaf(a, wa.w, acc[i][3]);
                acc[i][4] = fmaf(a, wb.x, acc[i][4]);
                acc[i][5] = fmaf(a, wb.y, acc[i][5]);
                acc[i][6] = fmaf(a, wb.z, acc[i][6]);
                acc[i][7] = fmaf(a, wb.w, acc[i][7]);
            }
        }
    }

    const float4 ba = *(const float4*)&bias[c0];
    const float4 bb = *(const float4*)&bias[c0 + 4];
    #pragma unroll
    for (int i = 0; i < 8; i++) {
        float4 oa, ob;
        float v;
        v = acc[i][0] + ba.x; oa.x = v / (1.f + __expf(-v));
        v = acc[i][1] + ba.y; oa.y = v / (1.f + __expf(-v));
        v = acc[i][2] + ba.z; oa.z = v / (1.f + __expf(-v));
        v = acc[i][3] + ba.w; oa.w = v / (1.f + __expf(-v));
        v = acc[i][4] + bb.x; ob.x = v / (1.f + __expf(-v));
        v = acc[i][5] + bb.y; ob.y = v / (1.f + __expf(-v));
        v = acc[i][6] + bb.z; ob.z = v / (1.f + __expf(-v));
        v = acc[i][7] + bb.w; ob.w = v / (1.f + __expf(-v));
        float* bp = &B[(i0 + r0 + i) * DIM + c0];
        *(float4*)bp = oa;
        *(float4*)(bp + 4) = ob;
    }
}

// ---------------------------------------------------------------------------
// Final projection: out[i] = sum_j A[i,j] * Wout[j]   (warp per node)
// ---------------------------------------------------------------------------
__global__ void out_kernel(const float* __restrict__ A,
                           const float* __restrict__ Wout,
                           float* __restrict__ out)
{
    const int node = blockIdx.x * 8 + (threadIdx.x >> 5);
    const int lane = threadIdx.x & 31;
    if (node >= N_NODES) return;
    const float4 w = *(const float4*)&Wout[lane * 4];
    const float4 v = *(const float4*)&A[(size_t)node * DIM + lane * 4];
    float s = v.x * w.x + v.y * w.y + v.z * w.z + v.w * w.w;
    #pragma unroll
    for (int o = 16; o; o >>= 1) s += __shfl_xor_sync(0xffffffffu, s, o);
    if (lane == 0) out[node] = s;
}

// ---------------------------------------------------------------------------
extern "C" void kernel_launch(void* const* d_in, const int* in_sizes, int n_in,
                              void* d_out, int out_size)
{
    const float* x    = (const float*)d_in[0];
    const float* rbf  = (const float*)d_in[1];
    const void*  idx  = d_in[2];
    const int wb = ((n_in >= 12) || (in_sizes[3] == 1)) ? 4 : 3;
    const float* Wrbf = (const float*)d_in[wb + 0];
    const float* W1   = (const float*)d_in[wb + 1];
    const float* b1   = (const float*)d_in[wb + 2];
    const float* W2   = (const float*)d_in[wb + 3];
    const float* b2   = (const float*)d_in[wb + 4];
    const float* W3   = (const float*)d_in[wb + 5];
    const float* b3   = (const float*)d_in[wb + 6];
    const float* Wout = (const float*)d_in[wb + 7];
    float* out = (float*)d_out;

    float *n0, *n1;
    cudaGetSymbolAddress((void**)&n0, g_nodes0);
    cudaGetSymbolAddress((void**)&n1, g_nodes1);

    cudaMemsetAsync(n0, 0, (size_t)N_NODES_PAD * DIM * sizeof(float));

    detect_idx_kernel<<<1, 1>>>((const int*)idx);

    edge_kernel<<<1184, 128>>>(x, rbf, idx, Wrbf);

    cudaFuncSetAttribute(layer_kernel,
                         cudaFuncAttributeMaxDynamicSharedMemorySize, L_SMEM_BYTES);

    const int lgrid = N_NODES_PAD / 128;  // 313
    layer_kernel<<<lgrid, 256, L_SMEM_BYTES>>>(n0, n1, W1, b1);
    layer_kernel<<<lgrid, 256, L_SMEM_BYTES>>>(n1, n0, W2, b2);
    layer_kernel<<<lgrid, 256, L_SMEM_BYTES>>>(n0, n1, W3, b3);

    out_kernel<<<(N_NODES + 7) / 8, 256>>>(n1, Wout, out);
}